// round 8
// baseline (speedup 1.0000x reference)
#include <cuda_runtime.h>
#include <cstdint>

#define NUM_RELS 500
#define N_NODES  200000
#define ENT_DIM  128

// Per-relation scalars padded to 8 floats (32B, one L2 sector):
//   [S_pp, 2*S_pr, 2*S_p, S_rr, 2*S_r, 0, 0, 0]
__device__ float4 g_rel_c[NUM_RELS * 2];
// Per-node scalars: x = emb_p . emb,  y = sum(emb)
__device__ float2 g_node_h[N_NODES];
__device__ float2 g_node_t[N_NODES];
// Referenced-node flags (0/1). Only ever set to 1 with the same index set on
// every call (fixed inputs) -> deterministic without clearing.
__device__ unsigned char g_h_flag[N_NODES];
__device__ unsigned char g_t_flag[N_NODES];

__device__ __forceinline__ float warp_sum(float v) {
    #pragma unroll
    for (int o = 16; o > 0; o >>= 1)
        v += __shfl_xor_sync(0xFFFFFFFFu, v, o);
    return v;
}

// Mark which nodes are actually referenced (head side / tail side).
__global__ __launch_bounds__(256)
void flag_kernel(const int* __restrict__ head_idx,
                 const int* __restrict__ tail_idx,
                 int B) {
    int i = blockIdx.x * blockDim.x + threadIdx.x;
    if (i >= B) return;
    g_h_flag[head_idx[i]] = 1;   // racy same-value stores: benign
    g_t_flag[tail_idx[i]] = 1;
}

// Fused precompute (1 node per warp, one-shot — best measured config).
// Skips the head-table pair / tail-table pair for nodes never referenced on
// that side (~8.2% each), cutting DRAM traffic.
//   warp <  N_NODES           : per-node scalars
//   warp in [N_NODES, +RELS)  : per-relation scalars
__global__ __launch_bounds__(256)
void precompute_kernel(const float* __restrict__ head_emb,
                       const float* __restrict__ head_emb_p,
                       const float* __restrict__ tail_emb,
                       const float* __restrict__ tail_emb_p,
                       const float* __restrict__ rel_emb,
                       const float* __restrict__ rel_emb_p) {
    int warp = (blockIdx.x * blockDim.x + threadIdx.x) >> 5;
    int lane = threadIdx.x & 31;

    if (warp < N_NODES) {
        int node = warp;
        bool need_h = (g_h_flag[node] != 0);   // uniform across warp
        bool need_t = (g_t_flag[node] != 0);
        if (!need_h && !need_t) return;

        size_t off = (size_t)node * ENT_DIM + lane * 4;

        float4 h  = make_float4(0.f, 0.f, 0.f, 0.f);
        float4 hp = h, t = h, tp = h;
        if (need_h) {
            h  = __ldcs(reinterpret_cast<const float4*>(head_emb   + off));
            hp = __ldcs(reinterpret_cast<const float4*>(head_emb_p + off));
        }
        if (need_t) {
            t  = __ldcs(reinterpret_cast<const float4*>(tail_emb   + off));
            tp = __ldcs(reinterpret_cast<const float4*>(tail_emb_p + off));
        }

        float ah = hp.x*h.x + hp.y*h.y + hp.z*h.z + hp.w*h.w;
        float bh = h.x + h.y + h.z + h.w;
        float at = tp.x*t.x + tp.y*t.y + tp.z*t.z + tp.w*t.w;
        float bt = t.x + t.y + t.z + t.w;

        ah = warp_sum(ah);
        bh = warp_sum(bh);
        at = warp_sum(at);
        bt = warp_sum(bt);

        if (lane == 0) {
            if (need_h) g_node_h[node] = make_float2(ah, bh);
            if (need_t) g_node_t[node] = make_float2(at, bt);
        }
    } else if (warp < N_NODES + NUM_RELS) {
        int rel = warp - N_NODES;
        const float4* r4 = reinterpret_cast<const float4*>(rel_emb   + (size_t)rel * ENT_DIM);
        const float4* p4 = reinterpret_cast<const float4*>(rel_emb_p + (size_t)rel * ENT_DIM);
        float4 q = __ldcs(r4 + lane);
        float4 p = __ldcs(p4 + lane);

        float s_pp = p.x*p.x + p.y*p.y + p.z*p.z + p.w*p.w;
        float s_pr = p.x*q.x + p.y*q.y + p.z*q.z + p.w*q.w;
        float s_p  = p.x + p.y + p.z + p.w;
        float s_rr = q.x*q.x + q.y*q.y + q.z*q.z + q.w*q.w;
        float s_r  = q.x + q.y + q.z + q.w;

        s_pp = warp_sum(s_pp);
        s_pr = warp_sum(s_pr);
        s_p  = warp_sum(s_p);
        s_rr = warp_sum(s_rr);
        s_r  = warp_sum(s_r);

        if (lane == 0) {
            g_rel_c[rel * 2 + 0] = make_float4(s_pp, 2.0f*s_pr, 2.0f*s_p, s_rr);
            g_rel_c[rel * 2 + 1] = make_float4(2.0f*s_r, 0.0f, 0.0f, 0.0f);
        }
    }
}

// One thread per batch row (best measured config, ~10.4us plateau).
__global__ __launch_bounds__(256)
void transd_score_kernel(const int* __restrict__ head_idx,
                         const int* __restrict__ tail_idx,
                         const int* __restrict__ rel_idx,
                         float* __restrict__ out,
                         int B) {
    int i = blockIdx.x * blockDim.x + threadIdx.x;
    if (i >= B) return;

    int hi = head_idx[i];
    int ti = tail_idx[i];
    int ri = rel_idx[i];

    float2 hc = __ldg(&g_node_h[hi]);
    float2 tc = __ldg(&g_node_t[ti]);
    float4 c0 = __ldg(&g_rel_c[ri * 2 + 0]);
    float4 c1 = __ldg(&g_rel_c[ri * 2 + 1]);

    float a = hc.x - tc.x;   // h_p.h - t_p.t
    float b = hc.y - tc.y;   // sum(h) - sum(t)

    // score = a^2*S_pp + a*(2S_pr) + ab*(2S_p) + S_rr + b*(2S_r) + D*b^2
    out[i] = a*a*c0.x + a*c0.y + a*b*c0.z
           + c0.w + b*c1.x + (float)ENT_DIM * b*b;
}

extern "C" void kernel_launch(void* const* d_in, const int* in_sizes, int n_in,
                              void* d_out, int out_size) {
    const float* head_emb   = (const float*)d_in[0];
    const float* head_emb_p = (const float*)d_in[1];
    const float* tail_emb   = (const float*)d_in[2];
    const float* tail_emb_p = (const float*)d_in[3];
    const float* rel_emb    = (const float*)d_in[4];
    const float* rel_emb_p  = (const float*)d_in[5];
    const int*   head_idx   = (const int*)d_in[6];
    const int*   tail_idx   = (const int*)d_in[7];
    const int*   rel_idx    = (const int*)d_in[8];
    float* out = (float*)d_out;

    int B = in_sizes[6];

    // Mark referenced nodes (head side / tail side).
    {
        int threads = 256;
        int blocks = (B + threads - 1) / threads;
        flag_kernel<<<blocks, threads>>>(head_idx, tail_idx, B);
    }

    // Fused per-node + per-relation precompute; skips unreferenced sides.
    {
        int threads = 256;                 // 8 warps/block
        long long warps = (long long)N_NODES + NUM_RELS;
        int blocks = (int)((warps * 32 + threads - 1) / threads);
        precompute_kernel<<<blocks, threads>>>(head_emb, head_emb_p,
                                               tail_emb, tail_emb_p,
                                               rel_emb, rel_emb_p);
    }

    // Closed-form score, one thread per row.
    {
        int threads = 256;
        int blocks = (B + threads - 1) / threads;
        transd_score_kernel<<<blocks, threads>>>(head_idx, tail_idx, rel_idx,
                                                 out, B);
    }
}

// round 9
// speedup vs baseline: 1.1589x; 1.1589x over previous
#include <cuda_runtime.h>
#include <cstdint>

#define NUM_RELS 500
#define N_NODES  200000
#define ENT_DIM  128

// Per-relation scalars: c0 = [S_pp, 2*S_pr, 2*S_p, S_rr], c1 = 2*S_r
__device__ float4 g_rel_c0[NUM_RELS];
__device__ float  g_rel_c1[NUM_RELS];
// Per-node scalars: x = emb_p . emb,  y = sum(emb)
__device__ float2 g_node_h[N_NODES];
__device__ float2 g_node_t[N_NODES];

__device__ __forceinline__ float warp_sum(float v) {
    #pragma unroll
    for (int o = 16; o > 0; o >>= 1)
        v += __shfl_xor_sync(0xFFFFFFFFu, v, o);
    return v;
}

// Fused precompute (1 node per warp, one-shot — best measured config):
//   warp <  N_NODES           : per-node scalars for all 4 entity tables
//   warp in [N_NODES, +RELS)  : per-relation scalars
__global__ __launch_bounds__(256)
void precompute_kernel(const float* __restrict__ head_emb,
                       const float* __restrict__ head_emb_p,
                       const float* __restrict__ tail_emb,
                       const float* __restrict__ tail_emb_p,
                       const float* __restrict__ rel_emb,
                       const float* __restrict__ rel_emb_p) {
    int warp = (blockIdx.x * blockDim.x + threadIdx.x) >> 5;
    int lane = threadIdx.x & 31;

    if (warp < N_NODES) {
        int node = warp;
        size_t off = (size_t)node * ENT_DIM + lane * 4;

        // Streaming loads: read-once data, evict-first.
        float4 h  = __ldcs(reinterpret_cast<const float4*>(head_emb   + off));
        float4 hp = __ldcs(reinterpret_cast<const float4*>(head_emb_p + off));
        float4 t  = __ldcs(reinterpret_cast<const float4*>(tail_emb   + off));
        float4 tp = __ldcs(reinterpret_cast<const float4*>(tail_emb_p + off));

        float ah = hp.x*h.x + hp.y*h.y + hp.z*h.z + hp.w*h.w;
        float bh = h.x + h.y + h.z + h.w;
        float at = tp.x*t.x + tp.y*t.y + tp.z*t.z + tp.w*t.w;
        float bt = t.x + t.y + t.z + t.w;

        ah = warp_sum(ah);
        bh = warp_sum(bh);
        at = warp_sum(at);
        bt = warp_sum(bt);

        if (lane == 0) {
            g_node_h[node] = make_float2(ah, bh);
            g_node_t[node] = make_float2(at, bt);
        }
    } else if (warp < N_NODES + NUM_RELS) {
        int rel = warp - N_NODES;
        const float4* r4 = reinterpret_cast<const float4*>(rel_emb   + (size_t)rel * ENT_DIM);
        const float4* p4 = reinterpret_cast<const float4*>(rel_emb_p + (size_t)rel * ENT_DIM);
        float4 q = __ldcs(r4 + lane);
        float4 p = __ldcs(p4 + lane);

        float s_pp = p.x*p.x + p.y*p.y + p.z*p.z + p.w*p.w;
        float s_pr = p.x*q.x + p.y*q.y + p.z*q.z + p.w*q.w;
        float s_p  = p.x + p.y + p.z + p.w;
        float s_rr = q.x*q.x + q.y*q.y + q.z*q.z + q.w*q.w;
        float s_r  = q.x + q.y + q.z + q.w;

        s_pp = warp_sum(s_pp);
        s_pr = warp_sum(s_pr);
        s_p  = warp_sum(s_p);
        s_rr = warp_sum(s_rr);
        s_r  = warp_sum(s_r);

        if (lane == 0) {
            // Fold the 2x factors so the score kernel does pure FMA.
            g_rel_c0[rel] = make_float4(s_pp, 2.0f*s_pr, 2.0f*s_p, s_rr);
            g_rel_c1[rel] = 2.0f*s_r;
        }
    }
}

// Persistent score kernel: rel-constant table staged in SMEM once per CTA
// (amortized over ~hundreds of rows per thread), node-scalar gathers via L2.
// Rel gathers become LDS (conflict deg ~4-8) instead of 32 L1tex wavefronts.
__global__ __launch_bounds__(256)
void transd_score_kernel(const int* __restrict__ head_idx,
                         const int* __restrict__ tail_idx,
                         const int* __restrict__ rel_idx,
                         float* __restrict__ out,
                         int B) {
    __shared__ float4 s_c0[NUM_RELS];   // 8 KB
    __shared__ float  s_c1[NUM_RELS];   // 2 KB

    for (int i = threadIdx.x; i < NUM_RELS; i += blockDim.x) {
        s_c0[i] = g_rel_c0[i];
        s_c1[i] = g_rel_c1[i];
    }
    __syncthreads();

    int stride = gridDim.x * blockDim.x;
    for (int i = blockIdx.x * blockDim.x + threadIdx.x; i < B; i += stride) {
        int hi = head_idx[i];
        int ti = tail_idx[i];
        int ri = rel_idx[i];

        float2 hc = __ldg(&g_node_h[hi]);
        float2 tc = __ldg(&g_node_t[ti]);
        float4 c0 = s_c0[ri];
        float  c1 = s_c1[ri];

        float a = hc.x - tc.x;   // h_p.h - t_p.t
        float b = hc.y - tc.y;   // sum(h) - sum(t)

        // score = a^2*S_pp + a*(2S_pr) + ab*(2S_p) + S_rr + b*(2S_r) + D*b^2
        out[i] = a*a*c0.x + a*c0.y + a*b*c0.z
               + c0.w + b*c1 + (float)ENT_DIM * b*b;
    }
}

extern "C" void kernel_launch(void* const* d_in, const int* in_sizes, int n_in,
                              void* d_out, int out_size) {
    const float* head_emb   = (const float*)d_in[0];
    const float* head_emb_p = (const float*)d_in[1];
    const float* tail_emb   = (const float*)d_in[2];
    const float* tail_emb_p = (const float*)d_in[3];
    const float* rel_emb    = (const float*)d_in[4];
    const float* rel_emb_p  = (const float*)d_in[5];
    const int*   head_idx   = (const int*)d_in[6];
    const int*   tail_idx   = (const int*)d_in[7];
    const int*   rel_idx    = (const int*)d_in[8];
    float* out = (float*)d_out;

    int B = in_sizes[6];

    // Fused per-node + per-relation precompute (streams all tables once).
    {
        int threads = 256;                 // 8 warps/block
        long long warps = (long long)N_NODES + NUM_RELS;
        int blocks = (int)((warps * 32 + threads - 1) / threads);
        precompute_kernel<<<blocks, threads>>>(head_emb, head_emb_p,
                                               tail_emb, tail_emb_p,
                                               rel_emb, rel_emb_p);
    }

    // Persistent score kernel: 8 CTAs/SM, grid-stride over rows.
    {
        int threads = 256;
        int blocks = 148 * 8;              // 1184 persistent CTAs
        transd_score_kernel<<<blocks, threads>>>(head_idx, tail_idx, rel_idx,
                                                 out, B);
    }
}